// round 11
// baseline (speedup 1.0000x reference)
#include <cuda_runtime.h>
#include <cstdint>

#define MM   6
#define BB   128
#define TT   32
#define DINN 64
#define HHH  512
#define EEE  512
#define NEMB 32

#define ROWS      32     // one batch per block
#define XS_STRIDE 68     // words; mod 32 = 4 -> conflict-free A-fragment LDS
#define HS_STRIDE 516    // words; mod 32 = 4

// per-warp weight ring: 2 stages x (8 rows x 272B)  (64 cols x 4B + 16B pad)
#define WROW_B   272
#define WSTG_B   (8 * WROW_B)            // 2176
#define WRING_B  (2 * WSTG_B)            // 4352
#define XS_BYTES (ROWS * XS_STRIDE * 4)  // 8704
#define HS_BYTES (ROWS * HS_STRIDE * 4)  // 66048
#define WR_OFF_B (XS_BYTES + HS_BYTES)   // 74752
#define SMEM_BYTES (WR_OFF_B + 8 * WRING_B)  // 109568

// batch order sorted by emb id (adjacent blocks share weight slices in L2)
__device__ int g_order[BB];

__global__ void pmst_prepass(const int* __restrict__ emb_ids) {
    const int e = threadIdx.x;             // 0..31, one thread per emb value
    int cnt = 0;
    for (int b = 0; b < BB; b++) cnt += (emb_ids[b] == e);
    int off = cnt;
    #pragma unroll
    for (int d = 1; d < 32; d <<= 1) {
        int v = __shfl_up_sync(0xFFFFFFFFu, off, d);
        if (e >= d) off += v;
    }
    int idx = off - cnt;
    for (int b = 0; b < BB; b++)
        if (emb_ids[b] == e) g_order[idx++] = b;
}

__device__ __forceinline__ uint32_t f2tf(float f) {
    uint32_t r; asm("cvt.rna.tf32.f32 %0, %1;" : "=r"(r) : "f"(f)); return r;
}

__device__ __forceinline__ void mma8(float* d, const uint32_t* a, uint32_t b0, uint32_t b1) {
    asm volatile(
        "mma.sync.aligned.m16n8k8.row.col.f32.tf32.tf32.f32 "
        "{%0,%1,%2,%3}, {%4,%5,%6,%7}, {%8,%9}, {%0,%1,%2,%3};"
        : "+f"(d[0]), "+f"(d[1]), "+f"(d[2]), "+f"(d[3])
        : "r"(a[0]), "r"(a[1]), "r"(a[2]), "r"(a[3]), "r"(b0), "r"(b1));
}

#define CP_COMMIT() asm volatile("cp.async.commit_group;" ::: "memory")
#define CP_WAIT1()  asm volatile("cp.async.wait_group 1;" ::: "memory")
#define CP_WAIT0()  asm volatile("cp.async.wait_group 0;" ::: "memory")

// Lane (g,tg) copies the 4x16B it reads back: rows (tg, tg+4), col-bytes 16g and 128+16g.
__device__ __forceinline__ void issue_wslab(uint32_t stage, const float* __restrict__ wrow,
                                            int g, int tg) {
    const float* s0 = wrow + (long)tg * 512 + 4 * g;        // row tg, cg0
    const float* s1 = s0 + 32;                               // row tg, cg1
    const float* s2 = s0 + 4 * 512;                          // row tg+4, cg0
    const float* s3 = s2 + 32;                               // row tg+4, cg1
    const uint32_t d0 = stage + (uint32_t)(tg * WROW_B + g * 16);
    asm volatile("cp.async.cg.shared.global [%0], [%1], 16;" :: "r"(d0),                   "l"(s0) : "memory");
    asm volatile("cp.async.cg.shared.global [%0], [%1], 16;" :: "r"(d0 + 128),             "l"(s1) : "memory");
    asm volatile("cp.async.cg.shared.global [%0], [%1], 16;" :: "r"(d0 + 4 * WROW_B),      "l"(s2) : "memory");
    asm volatile("cp.async.cg.shared.global [%0], [%1], 16;" :: "r"(d0 + 4 * WROW_B + 128),"l"(s3) : "memory");
}

__device__ __forceinline__ void lds128(float4& v, uint32_t addr) {
    asm volatile("ld.shared.v4.f32 {%0,%1,%2,%3}, [%4];"
                 : "=f"(v.x), "=f"(v.y), "=f"(v.z), "=f"(v.w) : "r"(addr));
}

// grid = (BB, MM); block = 256 threads (8 warps). Warp tile: 32 rows x 64 cols (2 col-groups).
// Column perm per 32-col group: logical mma col (8*nt + j) == physical (base + 4*j + nt).
__global__ __launch_bounds__(256, 2) void pmst_mma_kernel(
    const float* __restrict__ state,   // [B, T, M*DIN]
    const int*   __restrict__ emb_ids, // [B]
    const float* __restrict__ W1,      // [M, NEMB, DIN, H]
    const float* __restrict__ b1,      // [M, NEMB, H]
    const float* __restrict__ W2,      // [M, NEMB, H, E]
    const float* __restrict__ b2,      // [M, NEMB, E]
    const float* __restrict__ te,      // [M, E]
    float* __restrict__ out)           // [B, M*T, E]
{
    const int m = blockIdx.y;
    const int b = g_order[blockIdx.x];
    const int e = __ldg(emb_ids + b);

    extern __shared__ uint32_t smu[];
    uint32_t* Xs = smu;                        // [ROWS][XS_STRIDE]
    uint32_t* Hs = smu + ROWS * XS_STRIDE;     // [ROWS][HS_STRIDE]
    uint32_t smem_base;
    asm("{ .reg .u64 t; cvta.to.shared.u64 t, %1; cvt.u32.u64 %0, t; }"
        : "=r"(smem_base) : "l"((const void*)smu));

    const int tid  = threadIdx.x;
    const int wid  = tid >> 5;
    const int lane = tid & 31;
    const int g    = lane >> 2;    // 0..7
    const int tg   = lane & 3;     // 0..3

    const uint32_t wring = smem_base + WR_OFF_B + wid * WRING_B;
    const uint32_t wfrag = (uint32_t)(tg * WROW_B + g * 16);

    const long me = (long)m * NEMB + e;
    const float* W1p = W1 + me * (DINN * HHH);
    const float* W2p = W2 + me * ((long)HHH * EEE);
    const float* b1p = b1 + me * HHH;
    const float* b2p = b2 + me * EEE;
    const float* tep = te + (long)m * EEE;

    const int ncol0 = wid * 64;
    const float* w1base = W1p + ncol0;
    const float* w2base = W2p + ncol0;
    float acc[2][8][4];   // [m-tile][cg*4 + nt][frag]

    // ---- GEMM1 prologue: slabs 0,1 in flight ----
    issue_wslab(wring + 0 * WSTG_B, w1base,           g, tg); CP_COMMIT();
    issue_wslab(wring + 1 * WSTG_B, w1base + 8 * HHH, g, tg); CP_COMMIT();

    // ---- Stage X (32 x 64, tf32) ----
    #pragma unroll
    for (int i = tid; i < ROWS * DINN; i += 256) {
        const int t = i >> 6, k = i & 63;
        Xs[t * XS_STRIDE + k] =
            f2tf(__ldg(state + ((long)b * TT + t) * (MM * DINN) + m * DINN + k));
    }
    __syncthreads();

    // ================= GEMM1: H = relu(X @ W1 + b1) =================
    #pragma unroll
    for (int mt = 0; mt < 2; mt++)
        #pragma unroll
        for (int nt = 0; nt < 8; nt++)
            #pragma unroll
            for (int i = 0; i < 4; i++) acc[mt][nt][i] = 0.f;
    {
        #pragma unroll
        for (int kc = 0; kc < 8; kc++) {
            CP_WAIT1();
            // weight fragments (read before re-issuing into this slot)
            float4 v[4];
            const uint32_t baseA = wring + (kc & 1) * WSTG_B + wfrag;
            lds128(v[0], baseA);                       // row tg,   cg0
            lds128(v[1], baseA + 128);                 // row tg,   cg1
            lds128(v[2], baseA + 4 * WROW_B);          // row tg+4, cg0
            lds128(v[3], baseA + 4 * WROW_B + 128);    // row tg+4, cg1
            if (kc + 2 < 8) issue_wslab(wring + (kc & 1) * WSTG_B,
                                        w1base + (long)(kc + 2) * 8 * HHH, g, tg);
            CP_COMMIT();

            uint32_t a[2][4];
            {
                const uint32_t* xb = Xs + g * XS_STRIDE + tg + kc * 8;
                #pragma unroll
                for (int mt = 0; mt < 2; mt++) {
                    const uint32_t* xp = xb + mt * 16 * XS_STRIDE;
                    a[mt][0] = xp[0];
                    a[mt][1] = xp[8 * XS_STRIDE];
                    a[mt][2] = xp[4];
                    a[mt][3] = xp[8 * XS_STRIDE + 4];
                }
            }
            const uint32_t w0c0[4] = { f2tf(v[0].x), f2tf(v[0].y), f2tf(v[0].z), f2tf(v[0].w) };
            const uint32_t w0c1[4] = { f2tf(v[1].x), f2tf(v[1].y), f2tf(v[1].z), f2tf(v[1].w) };
            const uint32_t w1c0[4] = { f2tf(v[2].x), f2tf(v[2].y), f2tf(v[2].z), f2tf(v[2].w) };
            const uint32_t w1c1[4] = { f2tf(v[3].x), f2tf(v[3].y), f2tf(v[3].z), f2tf(v[3].w) };
            #pragma unroll
            for (int nt = 0; nt < 4; nt++)
                #pragma unroll
                for (int mt = 0; mt < 2; mt++) {
                    mma8(acc[mt][nt],     a[mt], w0c0[nt], w1c0[nt]);
                    mma8(acc[mt][4 + nt], a[mt], w0c1[nt], w1c1[nt]);
                }
        }
    }

    // ---- GEMM2 prologue (overlaps epilogue1 + barrier) ----
    CP_WAIT0();
    issue_wslab(wring + 0 * WSTG_B, w2base,           g, tg); CP_COMMIT();
    issue_wslab(wring + 1 * WSTG_B, w2base + 8 * EEE, g, tg); CP_COMMIT();

    // ---- epilogue1: relu + bias -> Hs at physical cols (8 contiguous per thread per cg) ----
    #pragma unroll
    for (int cg = 0; cg < 2; cg++) {
        const int pc = ncol0 + cg * 32 + 8 * tg;
        const float4 bL = __ldg((const float4*)(b1p + pc));
        const float4 bH = __ldg((const float4*)(b1p + pc + 4));
        #pragma unroll
        for (int mt = 0; mt < 2; mt++) {
            const int r0 = mt * 16 + g;
            const int r1 = r0 + 8;
            uint4 sl, sh;
            sl.x = f2tf(fmaxf(acc[mt][cg*4+0][0] + bL.x, 0.f));
            sl.y = f2tf(fmaxf(acc[mt][cg*4+1][0] + bL.y, 0.f));
            sl.z = f2tf(fmaxf(acc[mt][cg*4+2][0] + bL.z, 0.f));
            sl.w = f2tf(fmaxf(acc[mt][cg*4+3][0] + bL.w, 0.f));
            sh.x = f2tf(fmaxf(acc[mt][cg*4+0][1] + bH.x, 0.f));
            sh.y = f2tf(fmaxf(acc[mt][cg*4+1][1] + bH.y, 0.f));
            sh.z = f2tf(fmaxf(acc[mt][cg*4+2][1] + bH.z, 0.f));
            sh.w = f2tf(fmaxf(acc[mt][cg*4+3][1] + bH.w, 0.f));
            *(uint4*)(Hs + r0 * HS_STRIDE + pc)     = sl;
            *(uint4*)(Hs + r0 * HS_STRIDE + pc + 4) = sh;
            sl.x = f2tf(fmaxf(acc[mt][cg*4+0][2] + bL.x, 0.f));
            sl.y = f2tf(fmaxf(acc[mt][cg*4+1][2] + bL.y, 0.f));
            sl.z = f2tf(fmaxf(acc[mt][cg*4+2][2] + bL.z, 0.f));
            sl.w = f2tf(fmaxf(acc[mt][cg*4+3][2] + bL.w, 0.f));
            sh.x = f2tf(fmaxf(acc[mt][cg*4+0][3] + bH.x, 0.f));
            sh.y = f2tf(fmaxf(acc[mt][cg*4+1][3] + bH.y, 0.f));
            sh.z = f2tf(fmaxf(acc[mt][cg*4+2][3] + bH.z, 0.f));
            sh.w = f2tf(fmaxf(acc[mt][cg*4+3][3] + bH.w, 0.f));
            *(uint4*)(Hs + r1 * HS_STRIDE + pc)     = sl;
            *(uint4*)(Hs + r1 * HS_STRIDE + pc + 4) = sh;
        }
    }
    __syncthreads();

    // ================= GEMM2: Z = H @ W2 + b2 + te =================
    #pragma unroll
    for (int mt = 0; mt < 2; mt++)
        #pragma unroll
        for (int nt = 0; nt < 8; nt++)
            #pragma unroll
            for (int i = 0; i < 4; i++) acc[mt][nt][i] = 0.f;
    {
        #pragma unroll 4
        for (int kc = 0; kc < 64; kc++) {
            CP_WAIT1();
            float4 v[4];
            const uint32_t baseA = wring + (kc & 1) * WSTG_B + wfrag;
            lds128(v[0], baseA);
            lds128(v[1], baseA + 128);
            lds128(v[2], baseA + 4 * WROW_B);
            lds128(v[3], baseA + 4 * WROW_B + 128);
            if (kc + 2 < 64) issue_wslab(wring + (kc & 1) * WSTG_B,
                                         w2base + (long)(kc + 2) * 8 * EEE, g, tg);
            CP_COMMIT();

            uint32_t a[2][4];
            {
                const uint32_t* hb = Hs + g * HS_STRIDE + tg + kc * 8;
                #pragma unroll
                for (int mt = 0; mt < 2; mt++) {
                    const uint32_t* hp = hb + mt * 16 * HS_STRIDE;
                    a[mt][0] = hp[0];
                    a[mt][1] = hp[8 * HS_STRIDE];
                    a[mt][2] = hp[4];
                    a[mt][3] = hp[8 * HS_STRIDE + 4];
                }
            }
            const uint32_t w0c0[4] = { f2tf(v[0].x), f2tf(v[0].y), f2tf(v[0].z), f2tf(v[0].w) };
            const uint32_t w0c1[4] = { f2tf(v[1].x), f2tf(v[1].y), f2tf(v[1].z), f2tf(v[1].w) };
            const uint32_t w1c0[4] = { f2tf(v[2].x), f2tf(v[2].y), f2tf(v[2].z), f2tf(v[2].w) };
            const uint32_t w1c1[4] = { f2tf(v[3].x), f2tf(v[3].y), f2tf(v[3].z), f2tf(v[3].w) };
            #pragma unroll
            for (int nt = 0; nt < 4; nt++)
                #pragma unroll
                for (int mt = 0; mt < 2; mt++) {
                    mma8(acc[mt][nt],     a[mt], w0c0[nt], w1c0[nt]);
                    mma8(acc[mt][4 + nt], a[mt], w0c1[nt], w1c1[nt]);
                }
        }
    }

    // ---- epilogue2: out[b, m*T + t, physical col] ----
    {
        float* op = out + ((long)b * MM + m) * TT * EEE;
        #pragma unroll
        for (int cg = 0; cg < 2; cg++) {
            const int pc = ncol0 + cg * 32 + 8 * tg;
            const float4 bL = __ldg((const float4*)(b2p + pc));
            const float4 bH = __ldg((const float4*)(b2p + pc + 4));
            const float4 tL = __ldg((const float4*)(tep + pc));
            const float4 tH = __ldg((const float4*)(tep + pc + 4));
            const float4 aL = make_float4(bL.x + tL.x, bL.y + tL.y, bL.z + tL.z, bL.w + tL.w);
            const float4 aH = make_float4(bH.x + tH.x, bH.y + tH.y, bH.z + tH.z, bH.w + tH.w);
            #pragma unroll
            for (int mt = 0; mt < 2; mt++) {
                const int r0 = mt * 16 + g;
                const int r1 = r0 + 8;
                float* p0 = op + (long)r0 * EEE + pc;
                float* p1 = op + (long)r1 * EEE + pc;
                *(float4*)p0 = make_float4(acc[mt][cg*4+0][0] + aL.x, acc[mt][cg*4+1][0] + aL.y,
                                           acc[mt][cg*4+2][0] + aL.z, acc[mt][cg*4+3][0] + aL.w);
                *(float4*)(p0 + 4) = make_float4(acc[mt][cg*4+0][1] + aH.x, acc[mt][cg*4+1][1] + aH.y,
                                                 acc[mt][cg*4+2][1] + aH.z, acc[mt][cg*4+3][1] + aH.w);
                *(float4*)p1 = make_float4(acc[mt][cg*4+0][2] + aL.x, acc[mt][cg*4+1][2] + aL.y,
                                           acc[mt][cg*4+2][2] + aL.z, acc[mt][cg*4+3][2] + aL.w);
                *(float4*)(p1 + 4) = make_float4(acc[mt][cg*4+0][3] + aH.x, acc[mt][cg*4+1][3] + aH.y,
                                                 acc[mt][cg*4+2][3] + aH.z, acc[mt][cg*4+3][3] + aH.w);
            }
        }
    }
}

extern "C" void kernel_launch(void* const* d_in, const int* in_sizes, int n_in,
                              void* d_out, int out_size)
{
    const float* state   = (const float*)d_in[0];
    const int*   emb_ids = (const int*)  d_in[1];
    const float* W1      = (const float*)d_in[2];
    const float* b1      = (const float*)d_in[3];
    const float* W2      = (const float*)d_in[4];
    const float* b2      = (const float*)d_in[5];
    const float* te      = (const float*)d_in[6];
    float*       out     = (float*)d_out;

    pmst_prepass<<<1, 32>>>(emb_ids);

    cudaFuncSetAttribute(pmst_mma_kernel,
                         cudaFuncAttributeMaxDynamicSharedMemorySize, SMEM_BYTES);

    dim3 grid(BB, MM);
    pmst_mma_kernel<<<grid, 256, SMEM_BYTES>>>(state, emb_ids, W1, b1, W2, b2, te, out);
}